// round 2
// baseline (speedup 1.0000x reference)
#include <cuda_runtime.h>
#include <cuda_bf16.h>
#include <math.h>
#include <float.h>

#define BGR   32
#define NPER0 1024
#define N0    (BGR * NPER0)
#define HID   128
#define NE    524288
#define KK1   512
#define KK2   256
#define KK3   128
#define NC    10

// ---------------- scratch (static device memory) ----------------
__device__ __align__(16) float g_H[N0 * HID];
__device__ __align__(16) float g_X[N0 * HID];
__device__ __align__(16) float g_X2[N0 * HID];
__device__ float g_dinv[N0];
__device__ float g_deginv[N0];
__device__ float g_cat[N0];
__device__ float g_score[N0];
__device__ int   g_perm[N0];
__device__ int   g_nmap[N0];
__device__ int   g_cnt[N0];      // histogram
__device__ int   g_cur[N0];      // scatter cursors
__device__ int   g_rowptr[N0 + 1];
__device__ int   g_csr[NE];
__device__ int   g_srcA[NE], g_dstA[NE];
__device__ int   g_srcB[NE], g_dstB[NE];
__device__ int   g_ecnt[2];      // [0]=count of list A, [1]=count of list B
__device__ float g_r[BGR * 2 * HID];

static inline int ceil_div(int a, int b) { return (a + b - 1) / b; }

// ---------------- kernels ----------------
__global__ void k_zero_i(int* p, int count) {
    int i = blockIdx.x * blockDim.x + threadIdx.x;
    if (i < count) p[i] = 0;
}

__global__ void k_reset1(int* p) { *p = 0; }

// histogram of dst over active edges
__global__ void k_count(const int* __restrict__ dst, int* __restrict__ cnt,
                        const int* __restrict__ cntp, int cntv) {
    int n = cntp ? *cntp : cntv;
    int e = blockIdx.x * blockDim.x + threadIdx.x;
    if (e >= n) return;
    atomicAdd(&cnt[dst[e]], 1);
}

// single-block exclusive scan over cnt -> rowptr; also dinv/deginv; cursor init
__global__ void k_scan(const int* __restrict__ cnt, int n, int* __restrict__ rowptr,
                       float* __restrict__ dinv, float* __restrict__ deginv,
                       int* __restrict__ cursor) {
    __shared__ int ssum[1024];
    int t = threadIdx.x;
    int m = (n + 1023) >> 10;
    int begin = t * m;
    int end = min(begin + m, n);
    int local = 0;
    for (int i = begin; i < end; i++) local += cnt[i];
    ssum[t] = local;
    __syncthreads();
    for (int off = 1; off < 1024; off <<= 1) {
        int v = (t >= off) ? ssum[t - off] : 0;
        __syncthreads();
        ssum[t] += v;
        __syncthreads();
    }
    int prefix = (t == 0) ? 0 : ssum[t - 1];
    for (int i = begin; i < end; i++) {
        int c = cnt[i];
        rowptr[i] = prefix;
        cursor[i] = prefix;
        float deg = (float)(c + 1);
        dinv[i] = rsqrtf(deg);
        deginv[i] = 1.0f / deg;
        prefix += c;
    }
    if (t == 1023) rowptr[n] = prefix;
}

__global__ void k_scatter(const int* __restrict__ src, const int* __restrict__ dst,
                          int* __restrict__ cursor, int* __restrict__ csr,
                          const int* __restrict__ cntp, int cntv) {
    int n = cntp ? *cntp : cntv;
    int e = blockIdx.x * blockDim.x + threadIdx.x;
    if (e >= n) return;
    int d = dst[e];
    int slot = atomicAdd(&cursor[d], 1);
    csr[slot] = src[e];
}

// per-head projection: h[n, head*32+e] = sum_d x[n, head*32+d] * W[head, d, e]
__global__ void k_proj(const float* __restrict__ X, const float* __restrict__ W,
                       float* __restrict__ Hout, int n) {
    int t = threadIdx.x;
    int head = t >> 5, lane = t & 31;
    float wreg[32];
    #pragma unroll
    for (int d = 0; d < 32; d++) wreg[d] = W[head * 1024 + d * 32 + lane];
    int base = blockIdx.x * 64;
    int lim = min(n, base + 64);
    for (int node = base; node < lim; node++) {
        float xv = X[node * 128 + t];
        float acc = 0.f;
        #pragma unroll
        for (int d = 0; d < 32; d++)
            acc = fmaf(__shfl_sync(0xffffffffu, xv, d), wreg[d], acc);
        Hout[node * 128 + t] = acc;
    }
}

// gather aggregation: warp per dst node. Fuses: sym-norm agg + self loop + bias
// + relu  -> X ; then the per-head attention score projection -> catp.
__global__ void k_aggX(const float* __restrict__ H, const int* __restrict__ rowptr,
                       const int* __restrict__ csr, const float* __restrict__ dinv,
                       const float* __restrict__ deginv, const float* __restrict__ b,
                       const float* __restrict__ A, const float* __restrict__ psW,
                       float* __restrict__ X, float* __restrict__ catp, int n) {
    int d = blockIdx.x * (blockDim.x >> 5) + (threadIdx.x >> 5);
    int lane = threadIdx.x & 31;
    if (d >= n) return;
    int s0 = rowptr[d], s1 = rowptr[d + 1];
    float di = dinv[d];
    float4 acc = make_float4(0.f, 0.f, 0.f, 0.f);
    for (int j = s0; j < s1; j++) {
        int s = csr[j];
        float c = dinv[s] * di;
        float4 v = ((const float4*)(H + (size_t)s * 128))[lane];
        acc.x = fmaf(v.x, c, acc.x);
        acc.y = fmaf(v.y, c, acc.y);
        acc.z = fmaf(v.z, c, acc.z);
        acc.w = fmaf(v.w, c, acc.w);
    }
    float4 hv = ((const float4*)(H + (size_t)d * 128))[lane];
    float g2 = deginv[d];
    float4 bb = ((const float4*)b)[lane];
    float4 o;
    o.x = fmaxf(acc.x + hv.x * g2 + bb.x, 0.f);
    o.y = fmaxf(acc.y + hv.y * g2 + bb.y, 0.f);
    o.z = fmaxf(acc.z + hv.z * g2 + bb.z, 0.f);
    o.w = fmaxf(acc.w + hv.w * g2 + bb.w, 0.f);
    ((float4*)(X + (size_t)d * 128))[lane] = o;
    // attention score projection (catp = sum_f att[head(f)] * x[f] * psW[f])
    float4 av = ((const float4*)A)[lane];
    float att = o.x * av.x + o.y * av.y + o.z * av.z + o.w * av.w;
    att += __shfl_xor_sync(0xffffffffu, att, 1);
    att += __shfl_xor_sync(0xffffffffu, att, 2);
    att += __shfl_xor_sync(0xffffffffu, att, 4);
    float4 pw = ((const float4*)psW)[lane];
    float cc = att * (o.x * pw.x + o.y * pw.y + o.z * pw.z + o.w * pw.w);
    #pragma unroll
    for (int ofs = 16; ofs > 0; ofs >>= 1) cc += __shfl_xor_sync(0xffffffffu, cc, ofs);
    if (lane == 0) catp[d] = cc;
}

// scalar score aggregation (gather) + finalize
__global__ void k_saggscore(const float* __restrict__ catp, const int* __restrict__ rowptr,
                            const int* __restrict__ csr, const float* __restrict__ dinv,
                            const float* __restrict__ deginv, const float* __restrict__ psb,
                            float* __restrict__ score, int n) {
    int d = blockIdx.x * blockDim.x + threadIdx.x;
    if (d >= n) return;
    int s0 = rowptr[d], s1 = rowptr[d + 1];
    float acc = 0.f;
    for (int j = s0; j < s1; j++) {
        int s = csr[j];
        acc += catp[s] * dinv[s];
    }
    score[d] = acc * dinv[d] + catp[d] * deginv[d] + psb[0];
}

// per-graph bitonic sort (descending score, tie -> lower idx); also inits nmap
__global__ void k_sort_topk(const float* __restrict__ score, int nper, int k,
                            int* __restrict__ perm, int* __restrict__ nmap) {
    __shared__ float sk[1024];
    __shared__ int   si[1024];
    int tid = threadIdx.x;
    int base = blockIdx.x * nper;
    for (int i = tid; i < nper; i += blockDim.x) {
        sk[i] = score[base + i]; si[i] = i;
        nmap[base + i] = -1;
    }
    __syncthreads();
    for (int ks = 2; ks <= nper; ks <<= 1) {
        for (int j = ks >> 1; j > 0; j >>= 1) {
            for (int i = tid; i < nper; i += blockDim.x) {
                int ixj = i ^ j;
                if (ixj > i) {
                    float ka = sk[i], kb = sk[ixj];
                    int ia = si[i], ib = si[ixj];
                    bool a_before_b = (ka > kb) || (ka == kb && ia < ib);
                    bool dirUp = ((i & ks) == 0);
                    bool sw = dirUp ? (!a_before_b) : a_before_b;
                    if (sw) { sk[i] = kb; sk[ixj] = ka; si[i] = ib; si[ixj] = ia; }
                }
            }
            __syncthreads();
        }
    }
    for (int jj = tid; jj < k; jj += blockDim.x) {
        int oldg = base + si[jj];
        int nw = blockIdx.x * k + jj;
        perm[nw] = oldg;
        nmap[oldg] = nw;
    }
}

// fused gather (x[perm]*tanh(score)) + readout (max & mean) per graph
__global__ void k_pool(const float* __restrict__ X, const float* __restrict__ score,
                       const int* __restrict__ perm, float* __restrict__ Xout,
                       float* __restrict__ r, int k, int accum) {
    int g = blockIdx.x;
    int t = threadIdx.x;        // 512
    int f = t & 127, c = t >> 7;
    float mx = -FLT_MAX, sm = 0.f;
    for (int j = c; j < k; j += 4) {
        int node = g * k + j;
        int oldg = perm[node];
        float tv = tanhf(score[oldg]);
        float v = X[(size_t)oldg * 128 + f] * tv;
        Xout[(size_t)node * 128 + f] = v;
        mx = fmaxf(mx, v);
        sm += v;
    }
    __shared__ float smx[512], ssm[512];
    smx[t] = mx; ssm[t] = sm;
    __syncthreads();
    if (c == 0) {
        #pragma unroll
        for (int cc2 = 1; cc2 < 4; cc2++) {
            mx = fmaxf(mx, smx[cc2 * 128 + f]);
            sm += ssm[cc2 * 128 + f];
        }
        float o1 = mx, o2 = sm / (float)k;
        if (accum) { r[g * 256 + f] += o1; r[g * 256 + 128 + f] += o2; }
        else       { r[g * 256 + f]  = o1; r[g * 256 + 128 + f]  = o2; }
    }
}

// compact surviving edges (both endpoints kept) into remapped list
__global__ void k_compact(const int* __restrict__ srcI, const int* __restrict__ dstI,
                          const int* __restrict__ nmap, int* __restrict__ srcO,
                          int* __restrict__ dstO, int* __restrict__ cntOut,
                          const int* __restrict__ cntp, int cntv) {
    int n = cntp ? *cntp : cntv;
    int e = blockIdx.x * blockDim.x + threadIdx.x;
    if (e >= n) return;
    int ns = nmap[srcI[e]], nd = nmap[dstI[e]];
    if (ns >= 0 && nd >= 0) {
        int p = atomicAdd(cntOut, 1);
        srcO[p] = ns;
        dstO[p] = nd;
    }
}

__global__ void k_mlp(const float* __restrict__ r,
                      const float* __restrict__ l1W, const float* __restrict__ l1b,
                      const float* __restrict__ l2W, const float* __restrict__ l2b,
                      const float* __restrict__ l3W, const float* __restrict__ l3b,
                      float* __restrict__ out) {
    __shared__ float z0[256], z1[128], z2[64], z3[16];
    __shared__ float red2[2];
    int g = blockIdx.x, t = threadIdx.x;
    z0[t] = r[g * 256 + t];
    z0[t + 128] = r[g * 256 + 128 + t];
    __syncthreads();
    {
        float acc = l1b[t];
        for (int i = 0; i < 256; i++) acc = fmaf(z0[i], l1W[i * 128 + t], acc);
        z1[t] = fmaxf(acc, 0.f);
    }
    __syncthreads();
    if (t < 64) {
        float acc = l2b[t];
        for (int i = 0; i < 128; i++) acc = fmaf(z1[i], l2W[i * 64 + t], acc);
        z2[t] = fmaxf(acc, 0.f);
    }
    __syncthreads();
    if (t < NC) {
        float acc = l3b[t];
        for (int i = 0; i < 64; i++) acc = fmaf(z2[i], l3W[i * NC + t], acc);
        z3[t] = acc;
    }
    __syncthreads();
    if (t == 0) {
        float m = -FLT_MAX;
        for (int c = 0; c < NC; c++) m = fmaxf(m, z3[c]);
        float s = 0.f;
        for (int c = 0; c < NC; c++) s += expf(z3[c] - m);
        red2[0] = m; red2[1] = logf(s);
    }
    __syncthreads();
    if (t < NC) out[g * NC + t] = z3[t] - red2[0] - red2[1];
}

// ---------------- host side ----------------
struct Ptrs {
    float *H, *X, *X2, *dinv, *deginv, *cat, *score, *r;
    int *perm, *nmap, *cnt, *cur, *rowptr, *csr;
    int *srcA, *dstA, *srcB, *dstB, *ecnt;
};

static void run_stage(const Ptrs& P, const float* Xin, int n, int k,
                      const int* src, const int* dst, const int* cntp,
                      const float* W, const float* b, const float* A,
                      const float* psW, const float* psb,
                      float* Xpool, int accum,
                      bool doCompact, int* srcO, int* dstO, int* cntOut) {
    int nper = n / BGR;
    int egrid = ceil_div(NE, 256);     // upper bound for dynamic edge counts
    k_proj<<<ceil_div(n, 64), 128>>>(Xin, W, P.H, n);
    k_zero_i<<<ceil_div(n, 256), 256>>>(P.cnt, n);
    k_count<<<egrid, 256>>>(dst, P.cnt, cntp, NE);
    k_scan<<<1, 1024>>>(P.cnt, n, P.rowptr, P.dinv, P.deginv, P.cur);
    k_scatter<<<egrid, 256>>>(src, dst, P.cur, P.csr, cntp, NE);
    k_aggX<<<ceil_div(n, 8), 256>>>(P.H, P.rowptr, P.csr, P.dinv, P.deginv,
                                    b, A, psW, P.X, P.cat, n);
    k_saggscore<<<ceil_div(n, 256), 256>>>(P.cat, P.rowptr, P.csr, P.dinv,
                                           P.deginv, psb, P.score, n);
    k_sort_topk<<<BGR, 512>>>(P.score, nper, k, P.perm, P.nmap);
    k_pool<<<BGR, 512>>>(P.X, P.score, P.perm, Xpool, P.r, k, accum);
    if (doCompact) {
        k_reset1<<<1, 1>>>(cntOut);
        k_compact<<<egrid, 256>>>(src, dst, P.nmap, srcO, dstO, cntOut, cntp, NE);
    }
}

extern "C" void kernel_launch(void* const* d_in, const int* in_sizes, int n_in,
                              void* d_out, int out_size) {
    const float* x   = (const float*)d_in[0];
    const int*   src = (const int*)d_in[1];
    const int*   dst = (const int*)d_in[2];
    const float* W1 = (const float*)d_in[3];
    const float* b1 = (const float*)d_in[4];
    const float* A1 = (const float*)d_in[5];
    const float* ps1W = (const float*)d_in[6];
    const float* ps1b = (const float*)d_in[7];
    const float* W2 = (const float*)d_in[8];
    const float* b2 = (const float*)d_in[9];
    const float* A2 = (const float*)d_in[10];
    const float* ps2W = (const float*)d_in[11];
    const float* ps2b = (const float*)d_in[12];
    const float* W3 = (const float*)d_in[13];
    const float* b3 = (const float*)d_in[14];
    const float* A3 = (const float*)d_in[15];
    const float* ps3W = (const float*)d_in[16];
    const float* ps3b = (const float*)d_in[17];
    const float* l1W = (const float*)d_in[18];
    const float* l1b = (const float*)d_in[19];
    const float* l2W = (const float*)d_in[20];
    const float* l2b = (const float*)d_in[21];
    const float* l3W = (const float*)d_in[22];
    const float* l3b = (const float*)d_in[23];
    float* out = (float*)d_out;

    Ptrs P;
    cudaGetSymbolAddress((void**)&P.H, g_H);
    cudaGetSymbolAddress((void**)&P.X, g_X);
    cudaGetSymbolAddress((void**)&P.X2, g_X2);
    cudaGetSymbolAddress((void**)&P.dinv, g_dinv);
    cudaGetSymbolAddress((void**)&P.deginv, g_deginv);
    cudaGetSymbolAddress((void**)&P.cat, g_cat);
    cudaGetSymbolAddress((void**)&P.score, g_score);
    cudaGetSymbolAddress((void**)&P.r, g_r);
    cudaGetSymbolAddress((void**)&P.perm, g_perm);
    cudaGetSymbolAddress((void**)&P.nmap, g_nmap);
    cudaGetSymbolAddress((void**)&P.cnt, g_cnt);
    cudaGetSymbolAddress((void**)&P.cur, g_cur);
    cudaGetSymbolAddress((void**)&P.rowptr, g_rowptr);
    cudaGetSymbolAddress((void**)&P.csr, g_csr);
    cudaGetSymbolAddress((void**)&P.srcA, g_srcA);
    cudaGetSymbolAddress((void**)&P.dstA, g_dstA);
    cudaGetSymbolAddress((void**)&P.srcB, g_srcB);
    cudaGetSymbolAddress((void**)&P.dstB, g_dstB);
    cudaGetSymbolAddress((void**)&P.ecnt, g_ecnt);

    // stage 1: original edges (count = NE, static)
    run_stage(P, x, N0, KK1, src, dst, nullptr,
              W1, b1, A1, ps1W, ps1b, P.X2, /*accum=*/0,
              true, P.srcA, P.dstA, &P.ecnt[0]);
    // stage 2: compacted list A (dynamic count)
    run_stage(P, P.X2, BGR * KK1, KK2, P.srcA, P.dstA, &P.ecnt[0],
              W2, b2, A2, ps2W, ps2b, P.X2, /*accum=*/1,
              true, P.srcB, P.dstB, &P.ecnt[1]);
    // stage 3: compacted list B (dynamic count), no compaction afterwards
    run_stage(P, P.X2, BGR * KK2, KK3, P.srcB, P.dstB, &P.ecnt[1],
              W3, b3, A3, ps3W, ps3b, P.X2, /*accum=*/1,
              false, nullptr, nullptr, nullptr);

    k_mlp<<<BGR, 128>>>(P.r, l1W, l1b, l2W, l2b, l3W, l3b, out);
}

// round 3
// speedup vs baseline: 1.6274x; 1.6274x over previous
#include <cuda_runtime.h>
#include <cuda_bf16.h>
#include <math.h>
#include <float.h>

#define BGR   32
#define NPER0 1024
#define N0    (BGR * NPER0)
#define HID   128
#define NE    524288
#define KK1   512
#define KK2   256
#define KK3   128
#define NC    10
#define MAXDEG 128

// ---------------- scratch (static device memory) ----------------
__device__ __align__(16) float g_H[N0 * HID];
__device__ __align__(16) float g_X[N0 * HID];
__device__ __align__(16) float g_X2[N0 * HID];
__device__ float g_dinv[N0];
__device__ float g_deginv[N0];
__device__ float g_cat[N0];
__device__ float g_score[N0];
__device__ int   g_perm[N0];
__device__ int   g_nmap[N0];
__device__ int   g_cnt[N0];
__device__ int   g_csr[N0 * MAXDEG];
__device__ int   g_srcA[NE], g_dstA[NE];
__device__ int   g_srcB[NE], g_dstB[NE];
__device__ int   g_ecnt[2];
__device__ float g_r[BGR * 2 * HID];

static inline int ceil_div(int a, int b) { return (a + b - 1) / b; }

// ---------------- kernels ----------------
__global__ void k_zero_i(int* p, int count) {
    int i = blockIdx.x * blockDim.x + threadIdx.x;
    if (i < count) p[i] = 0;
}

__global__ void k_reset1(int* p) { *p = 0; }

// build fixed-stride CSR: slot = atomicAdd(cnt[d]); csr[d*MAXDEG+slot] = src
__global__ void k_build(const int* __restrict__ src, const int* __restrict__ dst,
                        int* __restrict__ cnt, int* __restrict__ csr,
                        const int* __restrict__ cntp, int cntv) {
    int n = cntp ? *cntp : cntv;
    int e = blockIdx.x * blockDim.x + threadIdx.x;
    if (e >= n) return;
    int d = dst[e];
    int slot = atomicAdd(&cnt[d], 1);
    if (slot < MAXDEG) csr[d * MAXDEG + slot] = src[e];
}

__global__ void k_dinv(const int* __restrict__ cnt, float* __restrict__ dinv,
                       float* __restrict__ deginv, int n) {
    int i = blockIdx.x * blockDim.x + threadIdx.x;
    if (i >= n) return;
    float deg = (float)(cnt[i] + 1);
    dinv[i] = rsqrtf(deg);
    deginv[i] = 1.0f / deg;
}

// per-head projection: h[n, head*32+e] = sum_d x[n, head*32+d] * W[head, d, e]
__global__ void k_proj(const float* __restrict__ X, const float* __restrict__ W,
                       float* __restrict__ Hout, int n) {
    int t = threadIdx.x;
    int head = t >> 5, lane = t & 31;
    float wreg[32];
    #pragma unroll
    for (int d = 0; d < 32; d++) wreg[d] = W[head * 1024 + d * 32 + lane];
    int base = blockIdx.x * 64;
    int lim = min(n, base + 64);
    for (int node = base; node < lim; node++) {
        float xv = X[node * 128 + t];
        float acc = 0.f;
        #pragma unroll
        for (int d = 0; d < 32; d++)
            acc = fmaf(__shfl_sync(0xffffffffu, xv, d), wreg[d], acc);
        Hout[node * 128 + t] = acc;
    }
}

// gather aggregation: warp per dst node. Fuses: sym-norm agg + self loop + bias
// + relu -> X ; then attention score projection -> catp.
__global__ void k_aggX(const float* __restrict__ H, const int* __restrict__ cnt,
                       const int* __restrict__ csr, const float* __restrict__ dinv,
                       const float* __restrict__ deginv, const float* __restrict__ b,
                       const float* __restrict__ A, const float* __restrict__ psW,
                       float* __restrict__ X, float* __restrict__ catp, int n) {
    int d = blockIdx.x * (blockDim.x >> 5) + (threadIdx.x >> 5);
    int lane = threadIdx.x & 31;
    if (d >= n) return;
    int deg = cnt[d];
    float di = dinv[d];
    const int* row = csr + (size_t)d * MAXDEG;
    float4 acc = make_float4(0.f, 0.f, 0.f, 0.f);
    for (int j = 0; j < deg; j++) {
        int s = row[j];
        float c = dinv[s] * di;
        float4 v = ((const float4*)(H + (size_t)s * 128))[lane];
        acc.x = fmaf(v.x, c, acc.x);
        acc.y = fmaf(v.y, c, acc.y);
        acc.z = fmaf(v.z, c, acc.z);
        acc.w = fmaf(v.w, c, acc.w);
    }
    float4 hv = ((const float4*)(H + (size_t)d * 128))[lane];
    float g2 = deginv[d];
    float4 bb = ((const float4*)b)[lane];
    float4 o;
    o.x = fmaxf(acc.x + hv.x * g2 + bb.x, 0.f);
    o.y = fmaxf(acc.y + hv.y * g2 + bb.y, 0.f);
    o.z = fmaxf(acc.z + hv.z * g2 + bb.z, 0.f);
    o.w = fmaxf(acc.w + hv.w * g2 + bb.w, 0.f);
    ((float4*)(X + (size_t)d * 128))[lane] = o;
    float4 av = ((const float4*)A)[lane];
    float att = o.x * av.x + o.y * av.y + o.z * av.z + o.w * av.w;
    att += __shfl_xor_sync(0xffffffffu, att, 1);
    att += __shfl_xor_sync(0xffffffffu, att, 2);
    att += __shfl_xor_sync(0xffffffffu, att, 4);
    float4 pw = ((const float4*)psW)[lane];
    float cc = att * (o.x * pw.x + o.y * pw.y + o.z * pw.z + o.w * pw.w);
    #pragma unroll
    for (int ofs = 16; ofs > 0; ofs >>= 1) cc += __shfl_xor_sync(0xffffffffu, cc, ofs);
    if (lane == 0) catp[d] = cc;
}

// scalar score aggregation (gather) + finalize
__global__ void k_saggscore(const float* __restrict__ catp, const int* __restrict__ cnt,
                            const int* __restrict__ csr, const float* __restrict__ dinv,
                            const float* __restrict__ deginv, const float* __restrict__ psb,
                            float* __restrict__ score, int n) {
    int d = blockIdx.x * blockDim.x + threadIdx.x;
    if (d >= n) return;
    int deg = cnt[d];
    const int* row = csr + (size_t)d * MAXDEG;
    float acc = 0.f;
    for (int j = 0; j < deg; j++) {
        int s = row[j];
        acc += catp[s] * dinv[s];
    }
    score[d] = acc * dinv[d] + catp[d] * deginv[d] + psb[0];
}

// per-graph bitonic sort (descending score, tie -> lower idx); also inits nmap
__global__ void k_sort_topk(const float* __restrict__ score, int nper, int k,
                            int* __restrict__ perm, int* __restrict__ nmap) {
    __shared__ float sk[1024];
    __shared__ int   si[1024];
    int tid = threadIdx.x;
    int base = blockIdx.x * nper;
    for (int i = tid; i < nper; i += blockDim.x) {
        sk[i] = score[base + i]; si[i] = i;
        nmap[base + i] = -1;
    }
    __syncthreads();
    for (int ks = 2; ks <= nper; ks <<= 1) {
        for (int j = ks >> 1; j > 0; j >>= 1) {
            for (int i = tid; i < nper; i += blockDim.x) {
                int ixj = i ^ j;
                if (ixj > i) {
                    float ka = sk[i], kb = sk[ixj];
                    int ia = si[i], ib = si[ixj];
                    bool a_before_b = (ka > kb) || (ka == kb && ia < ib);
                    bool dirUp = ((i & ks) == 0);
                    bool sw = dirUp ? (!a_before_b) : a_before_b;
                    if (sw) { sk[i] = kb; sk[ixj] = ka; si[i] = ib; si[ixj] = ia; }
                }
            }
            __syncthreads();
        }
    }
    for (int jj = tid; jj < k; jj += blockDim.x) {
        int oldg = base + si[jj];
        int nw = blockIdx.x * k + jj;
        perm[nw] = oldg;
        nmap[oldg] = nw;
    }
}

// fused gather (x[perm]*tanh(score)) + readout (max & mean) per graph
__global__ void k_pool(const float* __restrict__ X, const float* __restrict__ score,
                       const int* __restrict__ perm, float* __restrict__ Xout,
                       float* __restrict__ r, int k, int accum) {
    int g = blockIdx.x;
    int t = threadIdx.x;        // 512
    int f = t & 127, c = t >> 7;
    float mx = -FLT_MAX, sm = 0.f;
    for (int j = c; j < k; j += 4) {
        int node = g * k + j;
        int oldg = perm[node];
        float tv = tanhf(score[oldg]);
        float v = X[(size_t)oldg * 128 + f] * tv;
        Xout[(size_t)node * 128 + f] = v;
        mx = fmaxf(mx, v);
        sm += v;
    }
    __shared__ float smx[512], ssm[512];
    smx[t] = mx; ssm[t] = sm;
    __syncthreads();
    if (c == 0) {
        #pragma unroll
        for (int cc2 = 1; cc2 < 4; cc2++) {
            mx = fmaxf(mx, smx[cc2 * 128 + f]);
            sm += ssm[cc2 * 128 + f];
        }
        float o1 = mx, o2 = sm / (float)k;
        if (accum) { r[g * 256 + f] += o1; r[g * 256 + 128 + f] += o2; }
        else       { r[g * 256 + f]  = o1; r[g * 256 + 128 + f]  = o2; }
    }
}

// compact surviving edges into remapped list
__global__ void k_compact(const int* __restrict__ srcI, const int* __restrict__ dstI,
                          const int* __restrict__ nmap, int* __restrict__ srcO,
                          int* __restrict__ dstO, int* __restrict__ cntOut,
                          const int* __restrict__ cntp, int cntv) {
    int n = cntp ? *cntp : cntv;
    int e = blockIdx.x * blockDim.x + threadIdx.x;
    if (e >= n) return;
    int ns = nmap[srcI[e]], nd = nmap[dstI[e]];
    if (ns >= 0 && nd >= 0) {
        int p = atomicAdd(cntOut, 1);
        srcO[p] = ns;
        dstO[p] = nd;
    }
}

__global__ void k_mlp(const float* __restrict__ r,
                      const float* __restrict__ l1W, const float* __restrict__ l1b,
                      const float* __restrict__ l2W, const float* __restrict__ l2b,
                      const float* __restrict__ l3W, const float* __restrict__ l3b,
                      float* __restrict__ out) {
    __shared__ float z0[256], z1[128], z2[64], z3[16];
    __shared__ float red2[2];
    int g = blockIdx.x, t = threadIdx.x;
    z0[t] = r[g * 256 + t];
    z0[t + 128] = r[g * 256 + 128 + t];
    __syncthreads();
    {
        float acc = l1b[t];
        for (int i = 0; i < 256; i++) acc = fmaf(z0[i], l1W[i * 128 + t], acc);
        z1[t] = fmaxf(acc, 0.f);
    }
    __syncthreads();
    if (t < 64) {
        float acc = l2b[t];
        for (int i = 0; i < 128; i++) acc = fmaf(z1[i], l2W[i * 64 + t], acc);
        z2[t] = fmaxf(acc, 0.f);
    }
    __syncthreads();
    if (t < NC) {
        float acc = l3b[t];
        for (int i = 0; i < 64; i++) acc = fmaf(z2[i], l3W[i * NC + t], acc);
        z3[t] = acc;
    }
    __syncthreads();
    if (t == 0) {
        float m = -FLT_MAX;
        for (int c = 0; c < NC; c++) m = fmaxf(m, z3[c]);
        float s = 0.f;
        for (int c = 0; c < NC; c++) s += expf(z3[c] - m);
        red2[0] = m; red2[1] = logf(s);
    }
    __syncthreads();
    if (t < NC) out[g * NC + t] = z3[t] - red2[0] - red2[1];
}

// ---------------- host side ----------------
struct Ptrs {
    float *H, *X, *X2, *dinv, *deginv, *cat, *score, *r;
    int *perm, *nmap, *cnt, *csr;
    int *srcA, *dstA, *srcB, *dstB, *ecnt;
};

static void run_stage(const Ptrs& P, const float* Xin, int n, int k,
                      const int* src, const int* dst, const int* cntp,
                      const float* W, const float* b, const float* A,
                      const float* psW, const float* psb,
                      float* Xpool, int accum,
                      bool doCompact, int* srcO, int* dstO, int* cntOut) {
    int nper = n / BGR;
    int egrid = ceil_div(NE, 256);
    k_proj<<<ceil_div(n, 64), 128>>>(Xin, W, P.H, n);
    k_zero_i<<<ceil_div(n, 256), 256>>>(P.cnt, n);
    k_build<<<egrid, 256>>>(src, dst, P.cnt, P.csr, cntp, NE);
    k_dinv<<<ceil_div(n, 256), 256>>>(P.cnt, P.dinv, P.deginv, n);
    k_aggX<<<ceil_div(n, 8), 256>>>(P.H, P.cnt, P.csr, P.dinv, P.deginv,
                                    b, A, psW, P.X, P.cat, n);
    k_saggscore<<<ceil_div(n, 256), 256>>>(P.cat, P.cnt, P.csr, P.dinv,
                                           P.deginv, psb, P.score, n);
    k_sort_topk<<<BGR, 512>>>(P.score, nper, k, P.perm, P.nmap);
    k_pool<<<BGR, 512>>>(P.X, P.score, P.perm, Xpool, P.r, k, accum);
    if (doCompact) {
        k_reset1<<<1, 1>>>(cntOut);
        k_compact<<<egrid, 256>>>(src, dst, P.nmap, srcO, dstO, cntOut, cntp, NE);
    }
}

extern "C" void kernel_launch(void* const* d_in, const int* in_sizes, int n_in,
                              void* d_out, int out_size) {
    const float* x   = (const float*)d_in[0];
    const int*   src = (const int*)d_in[1];
    const int*   dst = (const int*)d_in[2];
    const float* W1 = (const float*)d_in[3];
    const float* b1 = (const float*)d_in[4];
    const float* A1 = (const float*)d_in[5];
    const float* ps1W = (const float*)d_in[6];
    const float* ps1b = (const float*)d_in[7];
    const float* W2 = (const float*)d_in[8];
    const float* b2 = (const float*)d_in[9];
    const float* A2 = (const float*)d_in[10];
    const float* ps2W = (const float*)d_in[11];
    const float* ps2b = (const float*)d_in[12];
    const float* W3 = (const float*)d_in[13];
    const float* b3 = (const float*)d_in[14];
    const float* A3 = (const float*)d_in[15];
    const float* ps3W = (const float*)d_in[16];
    const float* ps3b = (const float*)d_in[17];
    const float* l1W = (const float*)d_in[18];
    const float* l1b = (const float*)d_in[19];
    const float* l2W = (const float*)d_in[20];
    const float* l2b = (const float*)d_in[21];
    const float* l3W = (const float*)d_in[22];
    const float* l3b = (const float*)d_in[23];
    float* out = (float*)d_out;

    Ptrs P;
    cudaGetSymbolAddress((void**)&P.H, g_H);
    cudaGetSymbolAddress((void**)&P.X, g_X);
    cudaGetSymbolAddress((void**)&P.X2, g_X2);
    cudaGetSymbolAddress((void**)&P.dinv, g_dinv);
    cudaGetSymbolAddress((void**)&P.deginv, g_deginv);
    cudaGetSymbolAddress((void**)&P.cat, g_cat);
    cudaGetSymbolAddress((void**)&P.score, g_score);
    cudaGetSymbolAddress((void**)&P.r, g_r);
    cudaGetSymbolAddress((void**)&P.perm, g_perm);
    cudaGetSymbolAddress((void**)&P.nmap, g_nmap);
    cudaGetSymbolAddress((void**)&P.cnt, g_cnt);
    cudaGetSymbolAddress((void**)&P.csr, g_csr);
    cudaGetSymbolAddress((void**)&P.srcA, g_srcA);
    cudaGetSymbolAddress((void**)&P.dstA, g_dstA);
    cudaGetSymbolAddress((void**)&P.srcB, g_srcB);
    cudaGetSymbolAddress((void**)&P.dstB, g_dstB);
    cudaGetSymbolAddress((void**)&P.ecnt, g_ecnt);

    // stage 1: original edges (count = NE, static)
    run_stage(P, x, N0, KK1, src, dst, nullptr,
              W1, b1, A1, ps1W, ps1b, P.X2, /*accum=*/0,
              true, P.srcA, P.dstA, &P.ecnt[0]);
    // stage 2: compacted list A (dynamic count)
    run_stage(P, P.X2, BGR * KK1, KK2, P.srcA, P.dstA, &P.ecnt[0],
              W2, b2, A2, ps2W, ps2b, P.X2, /*accum=*/1,
              true, P.srcB, P.dstB, &P.ecnt[1]);
    // stage 3: compacted list B (dynamic count)
    run_stage(P, P.X2, BGR * KK2, KK3, P.srcB, P.dstB, &P.ecnt[1],
              W3, b3, A3, ps3W, ps3b, P.X2, /*accum=*/1,
              false, nullptr, nullptr, nullptr);

    k_mlp<<<BGR, 128>>>(P.r, l1W, l1b, l2W, l2b, l3W, l3b, out);
}

// round 4
// speedup vs baseline: 1.7156x; 1.0542x over previous
#include <cuda_runtime.h>
#include <cuda_bf16.h>
#include <math.h>
#include <float.h>

#define BGR   32
#define NPER0 1024
#define N0    (BGR * NPER0)
#define HID   128
#define NE    524288
#define KK1   512
#define KK2   256
#define KK3   128
#define NC    10
#define MAXDEG 128
#define N1    (BGR * KK1)
#define N2    (BGR * KK2)

// ---------------- scratch (static device memory) ----------------
__device__ __align__(16) float g_X[N0 * HID];     // post-layer features
__device__ __align__(16) float g_X2[N0 * HID];    // pooled features (stage input)
__device__ float g_dinv[N0];
__device__ float g_deginv[N0];
__device__ float g_catd[N0];      // catp * dinv
__device__ float g_catself[N0];   // catp * deginv
__device__ int   g_nmap[N0];
__device__ int   g_cnt0[N0];
__device__ int   g_cnt1[N1];
__device__ int   g_cnt2[N2];
__device__ int   g_csr[N0 * MAXDEG];
__device__ int   g_srcA[NE], g_dstA[NE];
__device__ int   g_srcB[NE], g_dstB[NE];
__device__ int   g_ecnt[2];
__device__ float g_r[BGR * 2 * HID];

static inline int ceil_div(int a, int b) { return (a + b - 1) / b; }

// ---------------- kernels ----------------
// zero all counters in one launch
__global__ void k_init(int* c0, int* c1, int* c2, int* ecnt) {
    int i = blockIdx.x * blockDim.x + threadIdx.x;
    if (i < N0) c0[i] = 0;
    if (i < N1) c1[i] = 0;
    if (i < N2) c2[i] = 0;
    if (i < 2)  ecnt[i] = 0;
}

// build fixed-stride CSR
__global__ void k_build(const int* __restrict__ src, const int* __restrict__ dst,
                        int* __restrict__ cnt, int* __restrict__ csr,
                        const int* __restrict__ cntp, int cntv) {
    int n = cntp ? *cntp : cntv;
    int e = blockIdx.x * blockDim.x + threadIdx.x;
    if (e >= n) return;
    int d = dst[e];
    int slot = atomicAdd(&cnt[d], 1);
    if (slot < MAXDEG) csr[d * MAXDEG + slot] = src[e];
}

__global__ void k_dinv(const int* __restrict__ cnt, float* __restrict__ dinv,
                       float* __restrict__ deginv, int n) {
    int i = blockIdx.x * blockDim.x + threadIdx.x;
    if (i >= n) return;
    float deg = (float)(cnt[i] + 1);
    dinv[i] = rsqrtf(deg);
    deginv[i] = 1.0f / deg;
}

// Mega-fused per-node kernel: aggregation of INPUT features (linearity:
// agg(X@W) = agg(X)@W), then per-head projection (W cols in registers,
// shuffle broadcast), bias+relu -> X ; attention score -> catd/catself.
// Block = 128 threads (warp == head), NPB nodes serially.
#define NPB 8
__global__ void k_aggXP(const float* __restrict__ Xin, const int* __restrict__ cnt,
                        const int* __restrict__ csr, const float* __restrict__ dinv,
                        const float* __restrict__ deginv, const float* __restrict__ W,
                        const float* __restrict__ b, const float* __restrict__ A,
                        const float* __restrict__ psW,
                        float* __restrict__ Xout, float* __restrict__ catd,
                        float* __restrict__ catself, int n) {
    int t = threadIdx.x;
    int head = t >> 5, lane = t & 31;
    float wreg[32];
    #pragma unroll
    for (int d = 0; d < 32; d++) wreg[d] = W[head * 1024 + d * 32 + lane];
    float av = A[t];
    float pw = psW[t];
    float bb = b[t];
    __shared__ float scat[4];
    int base = blockIdx.x * NPB;
    int lim = min(n, base + NPB);
    for (int node = base; node < lim; node++) {
        int deg = cnt[node];
        float di = dinv[node];
        float g2 = deginv[node];
        const int* row = csr + (size_t)node * MAXDEG;
        float acc = 0.f;
        int j = 0;
        for (; j + 4 <= deg; j += 4) {
            int s0 = row[j], s1 = row[j+1], s2 = row[j+2], s3 = row[j+3];
            float c0 = dinv[s0], c1 = dinv[s1], c2 = dinv[s2], c3 = dinv[s3];
            float x0 = Xin[(size_t)s0 * 128 + t];
            float x1 = Xin[(size_t)s1 * 128 + t];
            float x2 = Xin[(size_t)s2 * 128 + t];
            float x3 = Xin[(size_t)s3 * 128 + t];
            acc = fmaf(x0, c0, acc);
            acc = fmaf(x1, c1, acc);
            acc = fmaf(x2, c2, acc);
            acc = fmaf(x3, c3, acc);
        }
        for (; j < deg; j++) {
            int s = row[j];
            acc = fmaf(Xin[(size_t)s * 128 + t], dinv[s], acc);
        }
        float v = fmaf(acc, di, Xin[(size_t)node * 128 + t] * g2);
        // projection within head (warp): out = sum_d shfl(v,d) * wreg[d]
        float o = 0.f;
        #pragma unroll
        for (int d = 0; d < 32; d++)
            o = fmaf(__shfl_sync(0xffffffffu, v, d), wreg[d], o);
        o = fmaxf(o + bb, 0.f);
        Xout[(size_t)node * 128 + t] = o;
        // att[h] = warp sum of o*av
        float att = o * av;
        #pragma unroll
        for (int ofs = 16; ofs > 0; ofs >>= 1)
            att += __shfl_xor_sync(0xffffffffu, att, ofs);
        // catp partial = att * o * pw, warp reduce, block combine
        float cp = att * o * pw;
        #pragma unroll
        for (int ofs = 16; ofs > 0; ofs >>= 1)
            cp += __shfl_xor_sync(0xffffffffu, cp, ofs);
        if (lane == 0) scat[head] = cp;
        __syncthreads();
        if (t == 0) {
            float c = scat[0] + scat[1] + scat[2] + scat[3];
            catd[node] = c * di;
            catself[node] = c * g2;
        }
        __syncthreads();
    }
}

// Fused per-graph: score gather + bitonic sort + nmap + pool + readout
__global__ void k_select(const float* __restrict__ catd, const float* __restrict__ catself,
                         const float* __restrict__ dinv, const int* __restrict__ cnt,
                         const int* __restrict__ csr, const float* __restrict__ psb,
                         const float* __restrict__ Xmid, int* __restrict__ nmap,
                         float* __restrict__ Xpool, float* __restrict__ r,
                         int nper, int k, int accum) {
    __shared__ float sk[1024];
    __shared__ int   si[1024];
    __shared__ float smx[512], ssm[512];
    int g = blockIdx.x, t = threadIdx.x;   // 512 threads
    int base = g * nper;
    float pb = psb[0];
    for (int i = t; i < nper; i += 512) {
        int node = base + i;
        int deg = cnt[node];
        const int* row = csr + (size_t)node * MAXDEG;
        float acc = 0.f;
        for (int j = 0; j < deg; j++) acc += catd[row[j]];
        sk[i] = fmaf(acc, dinv[node], catself[node]) + pb;
        si[i] = i;
        nmap[node] = -1;
    }
    __syncthreads();
    for (int ks = 2; ks <= nper; ks <<= 1) {
        for (int j = ks >> 1; j > 0; j >>= 1) {
            for (int i = t; i < nper; i += 512) {
                int ixj = i ^ j;
                if (ixj > i) {
                    float ka = sk[i], kb = sk[ixj];
                    int ia = si[i], ib = si[ixj];
                    bool a_before_b = (ka > kb) || (ka == kb && ia < ib);
                    bool dirUp = ((i & ks) == 0);
                    bool sw = dirUp ? (!a_before_b) : a_before_b;
                    if (sw) { sk[i] = kb; sk[ixj] = ka; si[i] = ib; si[ixj] = ia; }
                }
            }
            __syncthreads();
        }
    }
    for (int jj = t; jj < k; jj += 512) nmap[base + si[jj]] = g * k + jj;
    // pool: v = X[orig]*tanh(score); write pooled; max/mean readout
    int f = t & 127, c = t >> 7;
    float mx = -FLT_MAX, sm = 0.f;
    for (int j = c; j < k; j += 4) {
        int orig = base + si[j];
        float tv = tanhf(sk[j]);
        float v = Xmid[(size_t)orig * 128 + f] * tv;
        Xpool[(size_t)(g * k + j) * 128 + f] = v;
        mx = fmaxf(mx, v);
        sm += v;
    }
    smx[t] = mx; ssm[t] = sm;
    __syncthreads();
    if (c == 0) {
        #pragma unroll
        for (int cc = 1; cc < 4; cc++) {
            mx = fmaxf(mx, smx[cc * 128 + f]);
            sm += ssm[cc * 128 + f];
        }
        float o1 = mx, o2 = sm / (float)k;
        if (accum) { r[g * 256 + f] += o1; r[g * 256 + 128 + f] += o2; }
        else       { r[g * 256 + f]  = o1; r[g * 256 + 128 + f]  = o2; }
    }
}

// compact surviving edges into remapped list
__global__ void k_compact(const int* __restrict__ srcI, const int* __restrict__ dstI,
                          const int* __restrict__ nmap, int* __restrict__ srcO,
                          int* __restrict__ dstO, int* __restrict__ cntOut,
                          const int* __restrict__ cntp, int cntv) {
    int n = cntp ? *cntp : cntv;
    int e = blockIdx.x * blockDim.x + threadIdx.x;
    if (e >= n) return;
    int ns = nmap[srcI[e]], nd = nmap[dstI[e]];
    if (ns >= 0 && nd >= 0) {
        int p = atomicAdd(cntOut, 1);
        srcO[p] = ns;
        dstO[p] = nd;
    }
}

__global__ void k_mlp(const float* __restrict__ r,
                      const float* __restrict__ l1W, const float* __restrict__ l1b,
                      const float* __restrict__ l2W, const float* __restrict__ l2b,
                      const float* __restrict__ l3W, const float* __restrict__ l3b,
                      float* __restrict__ out) {
    __shared__ float z0[256], z1[128], z2[64], z3[16];
    __shared__ float red2[2];
    int g = blockIdx.x, t = threadIdx.x;
    z0[t] = r[g * 256 + t];
    z0[t + 128] = r[g * 256 + 128 + t];
    __syncthreads();
    {
        float acc = l1b[t];
        for (int i = 0; i < 256; i++) acc = fmaf(z0[i], l1W[i * 128 + t], acc);
        z1[t] = fmaxf(acc, 0.f);
    }
    __syncthreads();
    if (t < 64) {
        float acc = l2b[t];
        for (int i = 0; i < 128; i++) acc = fmaf(z1[i], l2W[i * 64 + t], acc);
        z2[t] = fmaxf(acc, 0.f);
    }
    __syncthreads();
    if (t < NC) {
        float acc = l3b[t];
        for (int i = 0; i < 64; i++) acc = fmaf(z2[i], l3W[i * NC + t], acc);
        z3[t] = acc;
    }
    __syncthreads();
    if (t == 0) {
        float m = -FLT_MAX;
        for (int c = 0; c < NC; c++) m = fmaxf(m, z3[c]);
        float s = 0.f;
        for (int c = 0; c < NC; c++) s += expf(z3[c] - m);
        red2[0] = m; red2[1] = logf(s);
    }
    __syncthreads();
    if (t < NC) out[g * NC + t] = z3[t] - red2[0] - red2[1];
}

// ---------------- host side ----------------
struct Ptrs {
    float *X, *X2, *dinv, *deginv, *catd, *catself, *r;
    int *nmap, *cnt0, *cnt1, *cnt2, *csr;
    int *srcA, *dstA, *srcB, *dstB, *ecnt;
};

static void run_stage(const Ptrs& P, const float* Xin, int* cnt, int n, int k,
                      const int* src, const int* dst, const int* cntp,
                      const float* W, const float* b, const float* A,
                      const float* psW, const float* psb,
                      float* Xpool, int accum,
                      bool doCompact, int* srcO, int* dstO, int* cntOut) {
    int nper = n / BGR;
    int egrid = ceil_div(NE, 256);
    k_build<<<egrid, 256>>>(src, dst, cnt, P.csr, cntp, NE);
    k_dinv<<<ceil_div(n, 256), 256>>>(cnt, P.dinv, P.deginv, n);
    k_aggXP<<<ceil_div(n, NPB), 128>>>(Xin, cnt, P.csr, P.dinv, P.deginv,
                                       W, b, A, psW, P.X, P.catd, P.catself, n);
    k_select<<<BGR, 512>>>(P.catd, P.catself, P.dinv, cnt, P.csr, psb,
                           P.X, P.nmap, Xpool, P.r, nper, k, accum);
    if (doCompact)
        k_compact<<<egrid, 256>>>(src, dst, P.nmap, srcO, dstO, cntOut, cntp, NE);
}

extern "C" void kernel_launch(void* const* d_in, const int* in_sizes, int n_in,
                              void* d_out, int out_size) {
    const float* x   = (const float*)d_in[0];
    const int*   src = (const int*)d_in[1];
    const int*   dst = (const int*)d_in[2];
    const float* W1 = (const float*)d_in[3];
    const float* b1 = (const float*)d_in[4];
    const float* A1 = (const float*)d_in[5];
    const float* ps1W = (const float*)d_in[6];
    const float* ps1b = (const float*)d_in[7];
    const float* W2 = (const float*)d_in[8];
    const float* b2 = (const float*)d_in[9];
    const float* A2 = (const float*)d_in[10];
    const float* ps2W = (const float*)d_in[11];
    const float* ps2b = (const float*)d_in[12];
    const float* W3 = (const float*)d_in[13];
    const float* b3 = (const float*)d_in[14];
    const float* A3 = (const float*)d_in[15];
    const float* ps3W = (const float*)d_in[16];
    const float* ps3b = (const float*)d_in[17];
    const float* l1W = (const float*)d_in[18];
    const float* l1b = (const float*)d_in[19];
    const float* l2W = (const float*)d_in[20];
    const float* l2b = (const float*)d_in[21];
    const float* l3W = (const float*)d_in[22];
    const float* l3b = (const float*)d_in[23];
    float* out = (float*)d_out;

    Ptrs P;
    cudaGetSymbolAddress((void**)&P.X, g_X);
    cudaGetSymbolAddress((void**)&P.X2, g_X2);
    cudaGetSymbolAddress((void**)&P.dinv, g_dinv);
    cudaGetSymbolAddress((void**)&P.deginv, g_deginv);
    cudaGetSymbolAddress((void**)&P.catd, g_catd);
    cudaGetSymbolAddress((void**)&P.catself, g_catself);
    cudaGetSymbolAddress((void**)&P.r, g_r);
    cudaGetSymbolAddress((void**)&P.nmap, g_nmap);
    cudaGetSymbolAddress((void**)&P.cnt0, g_cnt0);
    cudaGetSymbolAddress((void**)&P.cnt1, g_cnt1);
    cudaGetSymbolAddress((void**)&P.cnt2, g_cnt2);
    cudaGetSymbolAddress((void**)&P.csr, g_csr);
    cudaGetSymbolAddress((void**)&P.srcA, g_srcA);
    cudaGetSymbolAddress((void**)&P.dstA, g_dstA);
    cudaGetSymbolAddress((void**)&P.srcB, g_srcB);
    cudaGetSymbolAddress((void**)&P.dstB, g_dstB);
    cudaGetSymbolAddress((void**)&P.ecnt, g_ecnt);

    k_init<<<ceil_div(N0, 256), 256>>>(P.cnt0, P.cnt1, P.cnt2, P.ecnt);

    // stage 1
    run_stage(P, x, P.cnt0, N0, KK1, src, dst, nullptr,
              W1, b1, A1, ps1W, ps1b, P.X2, /*accum=*/0,
              true, P.srcA, P.dstA, &P.ecnt[0]);
    // stage 2
    run_stage(P, P.X2, P.cnt1, N1, KK2, P.srcA, P.dstA, &P.ecnt[0],
              W2, b2, A2, ps2W, ps2b, P.X2, /*accum=*/1,
              true, P.srcB, P.dstB, &P.ecnt[1]);
    // stage 3
    run_stage(P, P.X2, P.cnt2, N2, KK3, P.srcB, P.dstB, &P.ecnt[1],
              W3, b3, A3, ps3W, ps3b, P.X2, /*accum=*/1,
              false, nullptr, nullptr, nullptr);

    k_mlp<<<BGR, 128>>>(P.r, l1W, l1b, l2W, l2b, l3W, l3b, out);
}